// round 1
// baseline (speedup 1.0000x reference)
#include <cuda_runtime.h>
#include <cstdint>

#define B_  16
#define T_  4096
#define D_  512
#define C_  10
#define FW_ 100
#define KW_ 201   // 2*FW+1

// ---------------- scratch (device globals; no allocations allowed) ----------
__device__ float g_bias[B_ * D_];          // b_enc[d] + (query @ W_dec.T)[b,d]
__device__ float g_conv[B_ * C_ * T_];     // [b][c][t]
__device__ float g_epart[B_ * T_ * 4];     // partial e per d-tile
__device__ float g_ctxp[B_ * 8 * D_];      // context partials per t-segment

// ---------------- helpers ---------------------------------------------------
__device__ __forceinline__ unsigned f2tf(float x) {
    unsigned u;
    asm("cvt.rna.tf32.f32 %0, %1;" : "=r"(u) : "f"(x));
    return u;
}

__device__ __forceinline__ void mma8(float& c0, float& c1, float& c2, float& c3,
                                     unsigned a0, unsigned a1, unsigned a2, unsigned a3,
                                     unsigned b0, unsigned b1) {
    asm volatile(
        "mma.sync.aligned.m16n8k8.row.col.f32.tf32.tf32.f32 "
        "{%0,%1,%2,%3}, {%4,%5,%6,%7}, {%8,%9}, {%0,%1,%2,%3};"
        : "+f"(c0), "+f"(c1), "+f"(c2), "+f"(c3)
        : "r"(a0), "r"(a1), "r"(a2), "r"(a3), "r"(b0), "r"(b1));
}

// ---------------- kernel 1: bias[b,d] = b_enc[d] + sum_k query[b,k]*W_dec[d,k]
__global__ __launch_bounds__(256)
void bias_kernel(const float* __restrict__ query, const float* __restrict__ W_dec,
                 const float* __restrict__ b_enc) {
    const int b = blockIdx.x;
    __shared__ float qS[D_];
    const int tid = threadIdx.x;
    qS[tid]       = query[b * D_ + tid];
    qS[tid + 256] = query[b * D_ + tid + 256];
    __syncthreads();
    const int warp = tid >> 5, lane = tid & 31;
    for (int r = warp; r < D_; r += 8) {
        float s = 0.f;
        const float* wp = W_dec + (size_t)r * D_;
        for (int k = lane; k < D_; k += 32) s += wp[k] * qS[k];
        #pragma unroll
        for (int o = 16; o > 0; o >>= 1) s += __shfl_xor_sync(0xffffffffu, s, o);
        if (lane == 0) g_bias[b * D_ + r] = s + b_enc[r];
    }
}

// ---------------- kernel 2: conv[b,c,t] = sum_k att_prev[b,t+k-FW]*W_conv[c,k]
__global__ __launch_bounds__(256)
void conv_kernel(const float* __restrict__ att_prev, const float* __restrict__ W_conv) {
    const int b  = blockIdx.y;
    const int t0 = blockIdx.x * 256;
    __shared__ float ap[256 + 2 * FW_];
    __shared__ float wS[C_ * KW_];
    const int tid = threadIdx.x;
    for (int i = tid; i < C_ * KW_; i += 256) wS[i] = W_conv[i];
    for (int i = tid; i < 256 + 2 * FW_; i += 256) {
        int t = t0 + i - FW_;
        ap[i] = (t >= 0 && t < T_) ? att_prev[(size_t)b * T_ + t] : 0.f;
    }
    __syncthreads();
    float acc[C_];
    #pragma unroll
    for (int cc = 0; cc < C_; cc++) acc[cc] = 0.f;
    for (int k = 0; k < KW_; k++) {
        float a = ap[tid + k];
        #pragma unroll
        for (int cc = 0; cc < C_; cc++) acc[cc] += a * wS[cc * KW_ + k];
    }
    const int t = t0 + tid;
    #pragma unroll
    for (int cc = 0; cc < C_; cc++)
        g_conv[((size_t)(b * C_ + cc)) * T_ + t] = acc[cc];
}

// ---------------- kernel 3: fused TF32 GEMM + tanh/w_g epilogue -------------
// Per block: 128 tokens x 128 d-outputs, K = 512 (value x W_enc) + 32-pad tail
// (cols 512..521 = conv x W_att, rest zero). Epilogue: x = acc + bias[d];
// p = w_g[d]*tanh(x); reduce p over the 128 d of this tile -> g_epart.
__global__ __launch_bounds__(256, 2)
void gemm_e_kernel(const float* __restrict__ value, const float* __restrict__ W_enc,
                   const float* __restrict__ W_att, const float* __restrict__ w_g) {
    const int b  = blockIdx.z;
    const int t0 = blockIdx.x * 128;
    const int d0 = blockIdx.y * 128;

    __shared__ __align__(16) unsigned As[128][36];
    __shared__ __align__(16) unsigned Bs[128][36];
    __shared__ float biasS[128];
    __shared__ float wgS[128];
    __shared__ float redS[128][4];

    const int tid  = threadIdx.x;
    const int lane = tid & 31;
    const int warp = tid >> 5;
    const int wm = warp >> 2;   // 0..1  (M half)
    const int wn = warp & 3;    // 0..3  (N quarter)
    const int g  = lane >> 2;   // 0..7
    const int q  = lane & 3;    // 0..3

    if (tid < 128) {
        biasS[tid] = g_bias[b * D_ + d0 + tid];
        wgS[tid]   = w_g[d0 + tid];
    }

    float c[4][4][4];
    #pragma unroll
    for (int mi = 0; mi < 4; mi++)
        #pragma unroll
        for (int ni = 0; ni < 4; ni++)
            #pragma unroll
            for (int e = 0; e < 4; e++) c[mi][ni][e] = 0.f;

    const float* Ag = value + ((size_t)b * T_ + t0) * D_;
    const float* Bg = W_enc + (size_t)d0 * D_;

    for (int kt = 0; kt < 17; ++kt) {
        __syncthreads();
        if (kt < 16) {
            const int k0 = kt * 32;
            #pragma unroll
            for (int i = 0; i < 4; i++) {
                int s  = tid + i * 256;       // 0..1023 float4 slots
                int r  = s >> 3;
                int cq = (s & 7) * 4;
                float4 av = *reinterpret_cast<const float4*>(Ag + (size_t)r * D_ + k0 + cq);
                *reinterpret_cast<uint4*>(&As[r][cq]) =
                    make_uint4(f2tf(av.x), f2tf(av.y), f2tf(av.z), f2tf(av.w));
                float4 bv = *reinterpret_cast<const float4*>(Bg + (size_t)r * D_ + k0 + cq);
                *reinterpret_cast<uint4*>(&Bs[r][cq]) =
                    make_uint4(f2tf(bv.x), f2tf(bv.y), f2tf(bv.z), f2tf(bv.w));
            }
        } else {
            // tail tile: A' cols = conv[b, c, t], B' cols = W_att[d, c], zero-padded
            #pragma unroll
            for (int i = 0; i < 16; i++) {
                int s  = tid + i * 256;       // 0..4095
                int r  = s >> 5;
                int cc = s & 31;
                float av = (cc < C_) ? g_conv[((size_t)(b * C_ + cc)) * T_ + t0 + r] : 0.f;
                As[r][cc] = f2tf(av);
                float bv = (cc < C_) ? W_att[(d0 + r) * C_ + cc] : 0.f;
                Bs[r][cc] = f2tf(bv);
            }
        }
        __syncthreads();

        #pragma unroll
        for (int k8 = 0; k8 < 4; k8++) {
            const int kb = k8 * 8;
            unsigned a[4][4], bfr[4][2];
            #pragma unroll
            for (int mi = 0; mi < 4; mi++) {
                int r = wm * 64 + mi * 16 + g;
                a[mi][0] = As[r    ][kb + q];
                a[mi][1] = As[r + 8][kb + q];
                a[mi][2] = As[r    ][kb + q + 4];
                a[mi][3] = As[r + 8][kb + q + 4];
            }
            #pragma unroll
            for (int ni = 0; ni < 4; ni++) {
                int n = wn * 32 + ni * 8 + g;
                bfr[ni][0] = Bs[n][kb + q];
                bfr[ni][1] = Bs[n][kb + q + 4];
            }
            #pragma unroll
            for (int mi = 0; mi < 4; mi++)
                #pragma unroll
                for (int ni = 0; ni < 4; ni++)
                    mma8(c[mi][ni][0], c[mi][ni][1], c[mi][ni][2], c[mi][ni][3],
                         a[mi][0], a[mi][1], a[mi][2], a[mi][3],
                         bfr[ni][0], bfr[ni][1]);
        }
    }

    // epilogue: tanh + w_g dot, reduce over this block's 128 d columns
    float rs[4][2];
    #pragma unroll
    for (int mi = 0; mi < 4; mi++) { rs[mi][0] = 0.f; rs[mi][1] = 0.f; }
    #pragma unroll
    for (int mi = 0; mi < 4; mi++)
        #pragma unroll
        for (int ni = 0; ni < 4; ni++)
            #pragma unroll
            for (int e = 0; e < 4; e++) {
                int dl  = wn * 32 + ni * 8 + q * 2 + (e & 1);
                float x = c[mi][ni][e] + biasS[dl];
                rs[mi][e >> 1] += wgS[dl] * tanhf(x);
            }
    #pragma unroll
    for (int mi = 0; mi < 4; mi++)
        #pragma unroll
        for (int h = 0; h < 2; h++) {
            float v = rs[mi][h];
            v += __shfl_xor_sync(0xffffffffu, v, 1);
            v += __shfl_xor_sync(0xffffffffu, v, 2);
            if (q == 0) redS[wm * 64 + mi * 16 + h * 8 + g][wn] = v;
        }
    __syncthreads();
    if (tid < 128) {
        float ev = redS[tid][0] + redS[tid][1] + redS[tid][2] + redS[tid][3];
        g_epart[((size_t)b * T_ + t0 + tid) * 4 + blockIdx.y] = ev;
    }
}

// ---------------- kernel 4: masked, sharpened softmax over T ----------------
__global__ __launch_bounds__(1024)
void softmax_kernel(const int* __restrict__ lens, float* __restrict__ out) {
    const int b   = blockIdx.x;
    const int len = lens[b];
    const int tid = threadIdx.x;
    __shared__ float sm[32];
    __shared__ float bc;

    float ev[4];
    float m = -1e30f;
    #pragma unroll
    for (int i = 0; i < 4; i++) {
        int t = tid + i * 1024;
        const float* p = &g_epart[((size_t)b * T_ + t) * 4];
        float e = p[0] + p[1] + p[2] + p[3];
        ev[i] = e;
        if (t < len) m = fmaxf(m, e);
    }
    #pragma unroll
    for (int o = 16; o > 0; o >>= 1) m = fmaxf(m, __shfl_xor_sync(0xffffffffu, m, o));
    if ((tid & 31) == 0) sm[tid >> 5] = m;
    __syncthreads();
    if (tid < 32) {
        float v = sm[tid];
        #pragma unroll
        for (int o = 16; o > 0; o >>= 1) v = fmaxf(v, __shfl_xor_sync(0xffffffffu, v, o));
        if (tid == 0) bc = v;
    }
    __syncthreads();
    const float M = bc;

    float s = 0.f;
    #pragma unroll
    for (int i = 0; i < 4; i++) {
        int t = tid + i * 1024;
        float w = (t < len) ? expf(2.0f * (ev[i] - M)) : 0.f;
        ev[i] = w;
        s += w;
    }
    #pragma unroll
    for (int o = 16; o > 0; o >>= 1) s += __shfl_xor_sync(0xffffffffu, s, o);
    __syncthreads();
    if ((tid & 31) == 0) sm[tid >> 5] = s;
    __syncthreads();
    if (tid < 32) {
        float v = sm[tid];
        #pragma unroll
        for (int o = 16; o > 0; o >>= 1) v += __shfl_xor_sync(0xffffffffu, v, o);
        if (tid == 0) bc = v;
    }
    __syncthreads();
    const float inv = 1.f / bc;
    #pragma unroll
    for (int i = 0; i < 4; i++) {
        int t = tid + i * 1024;
        out[B_ * D_ + (size_t)b * T_ + t] = ev[i] * inv;
    }
}

// ---------------- kernel 5: context partials over 8 t-segments --------------
__global__ __launch_bounds__(256)
void ctx_part_kernel(const float* __restrict__ value, const float* __restrict__ wts) {
    const int dch = blockIdx.x, seg = blockIdx.y, b = blockIdx.z;
    __shared__ float wS[512];
    const int tid = threadIdx.x;
    const int t0  = seg * 512;
    wS[tid]       = wts[(size_t)b * T_ + t0 + tid];
    wS[tid + 256] = wts[(size_t)b * T_ + t0 + tid + 256];
    __syncthreads();
    const int d = dch * 256 + tid;
    const float* vp = value + ((size_t)b * T_ + t0) * D_ + d;
    float acc = 0.f;
    #pragma unroll 8
    for (int t = 0; t < 512; t++) acc += vp[(size_t)t * D_] * wS[t];
    g_ctxp[((size_t)(b * 8 + seg)) * D_ + d] = acc;
}

// ---------------- kernel 6: context reduce ----------------------------------
__global__ __launch_bounds__(512)
void ctx_reduce_kernel(float* __restrict__ out) {
    const int b = blockIdx.x;
    const int d = threadIdx.x;
    float s = 0.f;
    #pragma unroll
    for (int seg = 0; seg < 8; seg++) s += g_ctxp[((size_t)(b * 8 + seg)) * D_ + d];
    out[b * D_ + d] = s;
}

// ---------------- launch -----------------------------------------------------
extern "C" void kernel_launch(void* const* d_in, const int* in_sizes, int n_in,
                              void* d_out, int out_size) {
    const float* value   = (const float*)d_in[0];
    const float* query   = (const float*)d_in[1];
    const int*   lens    = (const int*)  d_in[2];
    const float* attprev = (const float*)d_in[3];
    const float* W_enc   = (const float*)d_in[4];
    const float* b_enc   = (const float*)d_in[5];
    const float* W_dec   = (const float*)d_in[6];
    const float* W_att   = (const float*)d_in[7];
    const float* W_conv  = (const float*)d_in[8];
    const float* w_g     = (const float*)d_in[9];
    // d_in[10] = b_g: cancels exactly under softmax (constant shift) -> unused
    float* out = (float*)d_out;   // [0,8192) = context, [8192,73728) = att_weights

    bias_kernel<<<B_, 256>>>(query, W_dec, b_enc);
    conv_kernel<<<dim3(T_ / 256, B_), 256>>>(attprev, W_conv);
    gemm_e_kernel<<<dim3(T_ / 128, 4, B_), 256>>>(value, W_enc, W_att, w_g);
    softmax_kernel<<<B_, 1024>>>(lens, out);
    ctx_part_kernel<<<dim3(2, 8, B_), 256>>>(value, out + B_ * D_);
    ctx_reduce_kernel<<<B_, 512>>>(out);
}